// round 13
// baseline (speedup 1.0000x reference)
#include <cuda_runtime.h>

// Problem constants
#define HH   112
#define WW   112
#define CROP 28
#define CW   56
#define NPIX (CW * CW)
#define BB   128
#define MM   64
#define TT   12
#define HID  64
#define OUTD 36

#define NTHR 128
#define AUX_BLOCKS (BB * 2)      // 2 blocks per batch (28 rows each)
#define MOT_BLOCKS 4
#define NBLK (AUX_BLOCKS + MOT_BLOCKS)   // 260

__device__ float g_aux_partial[AUX_BLOCKS];
__device__ float g_mot_partial[MOT_BLOCKS];
__device__ int   g_count = 0;

#define FMA2(acc, x, y) \
    asm("fma.rn.f32x2 %0, %1, %2, %0;" : "+l"(acc) : "l"(x), "l"(y))

__global__ __launch_bounds__(NTHR) void fused_kernel(
    const int*   __restrict__ goal_pixel,   // [B,2] (col,row)
    const int*   __restrict__ obj_list,     // [B,M,2] (col,row)
    const int*   __restrict__ obj_num,      // [B]
    const int*   __restrict__ road_mask,    // [B,112,112]
    const float* __restrict__ logits,       // [B,56,56]
    const float* __restrict__ tpos,         // [B,T,2]
    const float* __restrict__ tyaw,         // [B,T]
    const float* __restrict__ w1, const float* __restrict__ b1,
    const float* __restrict__ w2, const float* __restrict__ b2,
    float*       __restrict__ out)
{
    const int blk = blockIdx.x;
    const int tid = threadIdx.x;

    __shared__ __align__(16) unsigned long long rowfd[MM * 28]; // 14KB dup'd
    __shared__ __align__(16) float colf[MM * 64];               // 16KB
    __shared__ float tabc[384];   // exp(-(i-112)^2/8); 0 for far indices
    __shared__ int   s_ox[MM], s_oy[MM];
    __shared__ float s_warp[4];
    __shared__ bool  s_last;

    if (blk < AUX_BLOCKS) {
        // ======== aux: 28 rows of one batch's 56x56 crop ========
        const int b  = blk >> 1;
        const int hf = blk & 1;             // row half
        const int rt = tid >> 4;            // row tile 0..7 (7 valid, 4 rows)
        const int ct = tid & 15;            // col tile 0..15 (14 valid, 4 cols)
        const int rteff = (rt < 7) ? rt : 6;
        const int cteff = (ct < 14) ? ct : 13;
        const int rbase = hf * 28;          // crop-row base of this block

        // ---- phase 0: front-issue ALL global loads into registers ----
        const int yg = goal_pixel[2 * b + 0];
        const int xg = goal_pixel[2 * b + 1];

        int2 ocoord = make_int2(-160, -160);
        int  nobj   = 0;
        if (tid < MM) {
            nobj   = obj_num[b];
            ocoord = ((const int2*)obj_list)[b * MM + tid];
        }

        const int r0e = rbase + rteff * 4, c0e = cteff * 4;
        float4 zreg[4];
        int4   mreg[4];
        {
            const float4* lg = (const float4*)(logits + b * NPIX + r0e * CW + c0e);
            const int4*   rm = (const int4*)(road_mask
                               + (b * HH + r0e + CROP) * WW + c0e + CROP);
            #pragma unroll
            for (int k = 0; k < 4; k++) {
                zreg[k] = __ldg(lg + k * (CW / 4));
                mreg[k] = __ldg(rm + k * (WW / 4));
            }
        }

        // ---- phase 1: tables ----
        for (int i = tid; i < 384; i += NTHR) {
            float d = (float)(i - 112);
            tabc[i] = __expf(-d * d * 0.125f);
        }
        if (tid < MM) {
            nobj = nobj < 0 ? 0 : (nobj > MM ? MM : nobj);
            if (tid >= nobj) { ocoord.x = -160; ocoord.y = -160; }
            s_ox[tid] = ocoord.x;   // col
            s_oy[tid] = ocoord.y;   // row
        }
        __syncthreads();

        // colf[m][c] = tab(c+28 - ox[m]), c in [0,64)
        for (int i = tid; i < MM * 64; i += NTHR) {
            const int m = i >> 6, c = i & 63;
            colf[i] = tabc[c + CROP + 112 - s_ox[m]];
        }
        // rowfd[m][r] = dup(tab(rbase+r+28 - oy[m])), r in [0,28)
        for (int i = tid; i < MM * 28; i += NTHR) {
            const int m = i / 28, r = i - m * 28;
            const float v = tabc[rbase + r + CROP + 112 - s_oy[m]];
            unsigned long long d;
            asm("mov.b64 %0, {%1, %1};" : "=l"(d) : "f"(v));
            rowfd[i] = d;
        }
        __syncthreads();

        // ---- phase 2: object loop (8 f32x2 accumulators, 4x4 px) ----
        unsigned long long a[8];
        #pragma unroll
        for (int i = 0; i < 8; i++) a[i] = 0ull;

        const ulonglong2* pc = ((const ulonglong2*)colf) + ct;         // +m*16
        const ulonglong2* pr = ((const ulonglong2*)rowfd) + rteff * 2; // +m*14

        #pragma unroll
        for (int m = 0; m < MM; m++) {
            const ulonglong2 cf  = pc[m * 16];      // (c0,c1),(c2,c3)
            const ulonglong2 r01 = pr[m * 14 + 0];  // dup r0, dup r1
            const ulonglong2 r23 = pr[m * 14 + 1];  // dup r2, dup r3
            FMA2(a[0], cf.x, r01.x); FMA2(a[1], cf.y, r01.x);
            FMA2(a[2], cf.x, r01.y); FMA2(a[3], cf.y, r01.y);
            FMA2(a[4], cf.x, r23.x); FMA2(a[5], cf.y, r23.x);
            FMA2(a[6], cf.x, r23.y); FMA2(a[7], cf.y, r23.y);
        }

        // ---- phase 3: epilogue from registers ----
        float local = 0.0f;
        if (rt < 7 && ct < 14) {
            const int r0 = rbase + rt * 4, c0 = ct * 4;
            float gc[4];
            #pragma unroll
            for (int u = 0; u < 4; u++)
                gc[u] = tabc[c0 + u + CROP + 112 - yg];

            #pragma unroll
            for (int k = 0; k < 4; k++) {
                const float4 z4 = zreg[k];
                const int4   m4 = mreg[k];
                const float  gr = tabc[r0 + k + CROP + 112 - xg];
                float s[4];
                asm("mov.b64 {%0, %1}, %2;" : "=f"(s[0]), "=f"(s[1]) : "l"(a[2*k]));
                asm("mov.b64 {%0, %1}, %2;" : "=f"(s[2]), "=f"(s[3]) : "l"(a[2*k+1]));
                const float zz[4] = {z4.x, z4.y, z4.z, z4.w};
                const int   mm[4] = {m4.x, m4.y, m4.z, m4.w};
                #pragma unroll
                for (int u = 0; u < 4; u++) {
                    const float z  = zz[u];
                    const float sp = fmaxf(z, 0.0f)
                                   + __logf(1.0f + __expf(-fabsf(z)));
                    float gt = 0.0f;
                    if (mm[u] != 0)
                        gt = 0.5f + 0.5f * (gc[u] * gr) - 0.5f * s[u];
                    local += sp - z * gt;
                }
            }
        }

        #pragma unroll
        for (int off = 16; off > 0; off >>= 1)
            local += __shfl_down_sync(0xffffffffu, local, off);
        if ((tid & 31) == 0) s_warp[tid >> 5] = local;
        __syncthreads();
        if (tid == 0)
            g_aux_partial[blk] = s_warp[0] + s_warp[1] + s_warp[2] + s_warp[3];
    } else {
        // ======== motion MLP loss (512 lanes over 4 blocks) ========
        const int mt = (blk - AUX_BLOCKS) * NTHR + tid;   // 0..511
        float part = 0.0f;
        {
            const int b  = mt >> 2;
            const int og = mt & 3;

            const float x0 = (float)goal_pixel[2 * b + 0];
            const float x1 = (float)goal_pixel[2 * b + 1];

            float h[HID];
            #pragma unroll
            for (int j = 0; j < HID; j++) {
                float v = fmaf(x0, w1[j], fmaf(x1, w1[HID + j], b1[j]));
                h[j] = fmaxf(v, 0.0f);
            }
            float acc[9];
            #pragma unroll
            for (int u = 0; u < 9; u++) acc[u] = b2[og * 9 + u];
            for (int j = 0; j < HID; j++) {
                const float hv = h[j];
                const float* wr = w2 + j * OUTD + og * 9;
                #pragma unroll
                for (int u = 0; u < 9; u++)
                    acc[u] = fmaf(hv, wr[u], acc[u]);
            }
            #pragma unroll
            for (int u = 0; u < 9; u++) {
                const int o = og * 9 + u;
                const int t = o / 3, uu = o % 3;
                const float tgt = (uu < 2) ? tpos[(b * TT + t) * 2 + uu]
                                           : tyaw[b * TT + t];
                const float d = acc[u] - tgt;
                part = fmaf(d, d, part);
            }
        }
        #pragma unroll
        for (int off = 16; off > 0; off >>= 1)
            part += __shfl_down_sync(0xffffffffu, part, off);
        if ((tid & 31) == 0) s_warp[tid >> 5] = part;
        __syncthreads();
        if (tid == 0)
            g_mot_partial[blk - AUX_BLOCKS] =
                s_warp[0] + s_warp[1] + s_warp[2] + s_warp[3];
    }

    // ======== last-block-done final combine ========
    __syncthreads();
    __threadfence();
    if (tid == 0) {
        int old = atomicAdd(&g_count, 1);
        s_last = (old == NBLK - 1);
    }
    __syncthreads();

    if (s_last) {
        __threadfence();
        float v = g_aux_partial[tid] + g_aux_partial[tid + 128];
        #pragma unroll
        for (int off = 16; off > 0; off >>= 1)
            v += __shfl_down_sync(0xffffffffu, v, off);
        if ((tid & 31) == 0) s_warp[tid >> 5] = v;
        __syncthreads();
        if (tid == 0) {
            const float aux = s_warp[0] + s_warp[1] + s_warp[2] + s_warp[3];
            const float mot = (g_mot_partial[0] + g_mot_partial[1]
                             + g_mot_partial[2] + g_mot_partial[3])
                              * (1.0f / (float)(BB * OUTD));
            out[0] = mot + aux;
            out[1] = aux;
            out[2] = mot;
            g_count = 0;   // reset for next graph replay
        }
    }
}

extern "C" void kernel_launch(void* const* d_in, const int* in_sizes, int n_in,
                              void* d_out, int out_size)
{
    const int*   goal_pixel = (const int*)  d_in[0];
    const int*   obj_list   = (const int*)  d_in[1];
    const int*   obj_num    = (const int*)  d_in[2];
    const int*   road_mask  = (const int*)  d_in[3];
    const float* logits     = (const float*)d_in[4];
    const float* tpos       = (const float*)d_in[5];
    const float* tyaw       = (const float*)d_in[6];
    const float* w1         = (const float*)d_in[7];
    const float* b1         = (const float*)d_in[8];
    const float* w2         = (const float*)d_in[9];
    const float* b2         = (const float*)d_in[10];
    float* out = (float*)d_out;

    fused_kernel<<<NBLK, NTHR>>>(goal_pixel, obj_list, obj_num, road_mask,
                                 logits, tpos, tyaw, w1, b1, w2, b2, out);
}

// round 14
// speedup vs baseline: 1.1800x; 1.1800x over previous
#include <cuda_runtime.h>

// Problem constants
#define HH   112
#define WW   112
#define CROP 28
#define CW   56
#define NPIX (CW * CW)
#define BB   128
#define MM   64
#define TT   12
#define HID  64
#define OUTD 36

#define NTHR 128
#define AUX_BLOCKS BB            // 1 block per batch
#define MOT_BLOCKS 4
#define NBLK (AUX_BLOCKS + MOT_BLOCKS)   // 132 <= 148 : one wave

__device__ float g_aux_partial[AUX_BLOCKS];
__device__ float g_mot_partial[MOT_BLOCKS];
__device__ int   g_count = 0;

#define FMA2(acc, x, y) \
    asm("fma.rn.f32x2 %0, %1, %2, %0;" : "+l"(acc) : "l"(x), "l"(y))

__global__ __launch_bounds__(NTHR) void fused_kernel(
    const int*   __restrict__ goal_pixel,   // [B,2] (col,row)
    const int*   __restrict__ obj_list,     // [B,M,2] (col,row)
    const int*   __restrict__ obj_num,      // [B]
    const int*   __restrict__ road_mask,    // [B,112,112]
    const float* __restrict__ logits,       // [B,56,56]
    const float* __restrict__ tpos,         // [B,T,2]
    const float* __restrict__ tyaw,         // [B,T]
    const float* __restrict__ w1, const float* __restrict__ b1,
    const float* __restrict__ w2, const float* __restrict__ b2,
    float*       __restrict__ out)
{
    const int blk = blockIdx.x;
    const int tid = threadIdx.x;

    __shared__ __align__(16) unsigned long long rowfd[MM * CW]; // 28KB dup'd
    __shared__ __align__(16) float colf[MM * 64];               // 16KB
    __shared__ float tabc[384];   // exp(-(i-112)^2/8); 0 for far indices
    __shared__ int   s_ox[MM], s_oy[MM];
    __shared__ int   s_list[4][MM];          // per-warp culled object indices
    __shared__ float s_warp[4];
    __shared__ bool  s_last;

    if (blk < AUX_BLOCKS) {
        // ======== aux: one full 56x56 crop per block ========
        const int b    = blk;
        const int rt   = tid >> 4;          // row tile 0..7 (7 valid, 8 rows)
        const int ct   = tid & 15;          // col tile 0..15 (14 valid, 4 cols)
        const int w    = tid >> 5;          // warp 0..3
        const int lane = tid & 31;
        const int rteff = (rt < 7) ? rt : 6;
        const int cteff = (ct < 14) ? ct : 13;

        // ---- phase 0: front-issue ALL global loads into registers ----
        const int yg = goal_pixel[2 * b + 0];
        const int xg = goal_pixel[2 * b + 1];

        int2 ocoord = make_int2(-160, -160);
        int  nobj   = 0;
        if (tid < MM) {
            nobj   = obj_num[b];
            ocoord = ((const int2*)obj_list)[b * MM + tid];
        }

        const int r0e = rteff * 8, c0e = cteff * 4;
        float4 zreg[8];
        int4   mreg[8];
        {
            const float4* lg = (const float4*)(logits + b * NPIX + r0e * CW + c0e);
            const int4*   rm = (const int4*)(road_mask
                               + (b * HH + r0e + CROP) * WW + c0e + CROP);
            #pragma unroll
            for (int k = 0; k < 8; k++) {
                zreg[k] = __ldg(lg + k * (CW / 4));
                mreg[k] = __ldg(rm + k * (WW / 4));
            }
        }

        // ---- phase 1: tables ----
        for (int i = tid; i < 384; i += NTHR) {
            float d = (float)(i - 112);
            tabc[i] = __expf(-d * d * 0.125f);
        }
        if (tid < MM) {
            nobj = nobj < 0 ? 0 : (nobj > MM ? MM : nobj);
            if (tid >= nobj) { ocoord.x = -160; ocoord.y = -160; }
            s_ox[tid] = ocoord.x;   // col
            s_oy[tid] = ocoord.y;   // row
        }
        __syncthreads();

        // colf[m][c] = tab(c+28 - ox[m]), c in [0,64)
        for (int i = tid; i < MM * 64; i += NTHR) {
            const int m = i >> 6, c = i & 63;
            colf[i] = tabc[c + CROP + 112 - s_ox[m]];
        }
        // rowfd[m][r] = dup(tab(r+28 - oy[m])), r in [0,56)
        for (int i = tid; i < MM * CW; i += NTHR) {
            const int m = i / CW, r = i - m * CW;
            const float v = tabc[r + CROP + 112 - s_oy[m]];
            unsigned long long d;
            asm("mov.b64 %0, {%1, %1};" : "=l"(d) : "f"(v));
            rowfd[i] = d;
        }

        // ---- per-warp object culling (Gaussian radius 13) ----
        // warp w covers global rows [28+16w, 28+16w+15] (w=3: [76,83])
        const int glo = CROP + 16 * w;
        const int ghi = (w == 3) ? 83 : (glo + 15);
        int cnt = 0;
        {
            #pragma unroll
            for (int base = 0; base < MM; base += 32) {
                const int m  = base + lane;
                const int oy = s_oy[m];
                const bool keep = (oy >= glo - 13) && (oy <= ghi + 13);
                const unsigned mask = __ballot_sync(0xffffffffu, keep);
                if (keep) {
                    const int pos = cnt + __popc(mask & ((1u << lane) - 1u));
                    s_list[w][pos] = m;
                }
                cnt += __popc(mask);
            }
        }
        __syncthreads();

        // ---- phase 2: object loop over culled list (16 f32x2 accs) ----
        unsigned long long a[16];
        #pragma unroll
        for (int i = 0; i < 16; i++) a[i] = 0ull;

        const ulonglong2* pc = ((const ulonglong2*)colf) + ct;         // +m*16
        const ulonglong2* pr = ((const ulonglong2*)rowfd) + rteff * 4; // +m*28
        const int* lst = s_list[w];

        #pragma unroll 4
        for (int i = 0; i < cnt; i++) {
            const int m = lst[i];
            const ulonglong2 cf  = pc[m * 16];      // (c0,c1),(c2,c3)
            const ulonglong2 r01 = pr[m * 28 + 0];
            const ulonglong2 r23 = pr[m * 28 + 1];
            const ulonglong2 r45 = pr[m * 28 + 2];
            const ulonglong2 r67 = pr[m * 28 + 3];
            FMA2(a[0],  cf.x, r01.x); FMA2(a[1],  cf.y, r01.x);
            FMA2(a[2],  cf.x, r01.y); FMA2(a[3],  cf.y, r01.y);
            FMA2(a[4],  cf.x, r23.x); FMA2(a[5],  cf.y, r23.x);
            FMA2(a[6],  cf.x, r23.y); FMA2(a[7],  cf.y, r23.y);
            FMA2(a[8],  cf.x, r45.x); FMA2(a[9],  cf.y, r45.x);
            FMA2(a[10], cf.x, r45.y); FMA2(a[11], cf.y, r45.y);
            FMA2(a[12], cf.x, r67.x); FMA2(a[13], cf.y, r67.x);
            FMA2(a[14], cf.x, r67.y); FMA2(a[15], cf.y, r67.y);
        }

        // ---- phase 3: epilogue from registers ----
        float local = 0.0f;
        if (rt < 7 && ct < 14) {
            const int r0 = rt * 8, c0 = ct * 4;
            float gc[4];
            #pragma unroll
            for (int u = 0; u < 4; u++)
                gc[u] = tabc[c0 + u + CROP + 112 - yg];

            #pragma unroll
            for (int k = 0; k < 8; k++) {
                const float4 z4 = zreg[k];
                const int4   m4 = mreg[k];
                const float  gr = tabc[r0 + k + CROP + 112 - xg];
                float s[4];
                asm("mov.b64 {%0, %1}, %2;" : "=f"(s[0]), "=f"(s[1]) : "l"(a[2*k]));
                asm("mov.b64 {%0, %1}, %2;" : "=f"(s[2]), "=f"(s[3]) : "l"(a[2*k+1]));
                const float zz[4] = {z4.x, z4.y, z4.z, z4.w};
                const int   mm[4] = {m4.x, m4.y, m4.z, m4.w};
                #pragma unroll
                for (int u = 0; u < 4; u++) {
                    const float z  = zz[u];
                    const float sp = fmaxf(z, 0.0f)
                                   + __logf(1.0f + __expf(-fabsf(z)));
                    float gt = 0.0f;
                    if (mm[u] != 0)
                        gt = 0.5f + 0.5f * (gc[u] * gr) - 0.5f * s[u];
                    local += sp - z * gt;
                }
            }
        }

        #pragma unroll
        for (int off = 16; off > 0; off >>= 1)
            local += __shfl_down_sync(0xffffffffu, local, off);
        if ((tid & 31) == 0) s_warp[tid >> 5] = local;
        __syncthreads();
        if (tid == 0)
            g_aux_partial[blk] = s_warp[0] + s_warp[1] + s_warp[2] + s_warp[3];
    } else {
        // ======== motion MLP loss (512 lanes over 4 blocks) ========
        const int mt = (blk - AUX_BLOCKS) * NTHR + tid;   // 0..511
        float part = 0.0f;
        {
            const int b  = mt >> 2;
            const int og = mt & 3;

            const float x0 = (float)goal_pixel[2 * b + 0];
            const float x1 = (float)goal_pixel[2 * b + 1];

            float h[HID];
            #pragma unroll
            for (int j = 0; j < HID; j++) {
                float v = fmaf(x0, w1[j], fmaf(x1, w1[HID + j], b1[j]));
                h[j] = fmaxf(v, 0.0f);
            }
            float acc[9];
            #pragma unroll
            for (int u = 0; u < 9; u++) acc[u] = b2[og * 9 + u];
            for (int j = 0; j < HID; j++) {
                const float hv = h[j];
                const float* wr = w2 + j * OUTD + og * 9;
                #pragma unroll
                for (int u = 0; u < 9; u++)
                    acc[u] = fmaf(hv, wr[u], acc[u]);
            }
            #pragma unroll
            for (int u = 0; u < 9; u++) {
                const int o = og * 9 + u;
                const int t = o / 3, uu = o % 3;
                const float tgt = (uu < 2) ? tpos[(b * TT + t) * 2 + uu]
                                           : tyaw[b * TT + t];
                const float d = acc[u] - tgt;
                part = fmaf(d, d, part);
            }
        }
        #pragma unroll
        for (int off = 16; off > 0; off >>= 1)
            part += __shfl_down_sync(0xffffffffu, part, off);
        if ((tid & 31) == 0) s_warp[tid >> 5] = part;
        __syncthreads();
        if (tid == 0)
            g_mot_partial[blk - AUX_BLOCKS] =
                s_warp[0] + s_warp[1] + s_warp[2] + s_warp[3];
    }

    // ======== last-block-done final combine ========
    __syncthreads();
    __threadfence();
    if (tid == 0) {
        int old = atomicAdd(&g_count, 1);
        s_last = (old == NBLK - 1);
    }
    __syncthreads();

    if (s_last) {
        __threadfence();
        float v = g_aux_partial[tid];        // 128 partials, 1 per thread
        #pragma unroll
        for (int off = 16; off > 0; off >>= 1)
            v += __shfl_down_sync(0xffffffffu, v, off);
        if ((tid & 31) == 0) s_warp[tid >> 5] = v;
        __syncthreads();
        if (tid == 0) {
            const float aux = s_warp[0] + s_warp[1] + s_warp[2] + s_warp[3];
            const float mot = (g_mot_partial[0] + g_mot_partial[1]
                             + g_mot_partial[2] + g_mot_partial[3])
                              * (1.0f / (float)(BB * OUTD));
            out[0] = mot + aux;
            out[1] = aux;
            out[2] = mot;
            g_count = 0;   // reset for next graph replay
        }
    }
}

extern "C" void kernel_launch(void* const* d_in, const int* in_sizes, int n_in,
                              void* d_out, int out_size)
{
    const int*   goal_pixel = (const int*)  d_in[0];
    const int*   obj_list   = (const int*)  d_in[1];
    const int*   obj_num    = (const int*)  d_in[2];
    const int*   road_mask  = (const int*)  d_in[3];
    const float* logits     = (const float*)d_in[4];
    const float* tpos       = (const float*)d_in[5];
    const float* tyaw       = (const float*)d_in[6];
    const float* w1         = (const float*)d_in[7];
    const float* b1         = (const float*)d_in[8];
    const float* w2         = (const float*)d_in[9];
    const float* b2         = (const float*)d_in[10];
    float* out = (float*)d_out;

    fused_kernel<<<NBLK, NTHR>>>(goal_pixel, obj_list, obj_num, road_mask,
                                 logits, tpos, tyaw, w1, b1, w2, b2, out);
}